// round 11
// baseline (speedup 1.0000x reference)
#include <cuda_runtime.h>
#include <cuda_bf16.h>
#include <math.h>

// ---------------- problem constants ----------------
#define D        128
#define NTYPES   6
#define NLAYERS  4
#define NRELS    10
#define E_LABEL  200000
#define NTOT     146000

// node types: 0=patient 1=visit 2=symptom 3=procedure 4=disease 5=drug
static const int kN[NTYPES]   = {20000, 100000, 4000, 8000, 10000, 4000};
static const int kOFF[NTYPES] = {0, 20000, 120000, 124000, 132000, 142000};

// relations (src,dst,E): order matches EI_NAMES
static const int kRS[NRELS] = {0,1,1,2,1,3,1,4,1,5};
static const int kRD[NRELS] = {1,0,2,1,3,1,4,1,5,1};
static const int kRE[NRELS] = {100000,100000,300000,300000,200000,200000,250000,250000,300000,300000};

// ---------------- static device scratch ----------------
__device__ float g_x0[(size_t)NTOT * D];
__device__ float g_x1[(size_t)NTOT * D];
__device__ float g_agg[(size_t)100000 * D];     // per-relation mean numerator (max dst = visit)
__device__ float g_deg[100000];
__device__ float g_wre[(size_t)NLAYERS * NTYPES * D * D]; // sum of tf32(W_r) per (layer, dst type)
__device__ float g_bef[(size_t)NLAYERS * NTYPES * D];
__device__ float g_part[256];

__device__ const int c_relcnt[NTYPES]  = {1, 5, 1, 1, 1, 1};
__device__ const int c_rels[NTYPES][5] = {{1,0,0,0,0},{0,3,5,7,9},{2,0,0,0,0},
                                          {4,0,0,0,0},{6,0,0,0,0},{8,0,0,0,0}};

// tf32 rounding as done by cuBLAS/CUTLASS (cvt.rna.tf32.f32): fp32 value with
// mantissa rounded to 10 bits. Reproduces XLA:GPU's default f32 matmul inputs.
__device__ __forceinline__ float tf32r(float x) {
    unsigned u;
    asm("cvt.rna.tf32.f32 %0, %1;" : "=r"(u) : "f"(x));
    return __uint_as_float(u);
}

// ---------------- utility kernels ----------------
__global__ void kzero(float* __restrict__ p, size_t n) {
    size_t i = (size_t)blockIdx.x * blockDim.x + threadIdx.x;
    size_t s = (size_t)gridDim.x * blockDim.x;
    for (; i < n; i += s) p[i] = 0.f;
}

__global__ void krelu(float* __restrict__ p, size_t n) {
    size_t i = (size_t)blockIdx.x * blockDim.x + threadIdx.x;
    size_t s = (size_t)gridDim.x * blockDim.x;
    for (; i < n; i += s) p[i] = fmaxf(p[i], 0.f);
}

// Sum tf32-rounded W_r over relations targeting each dst type (per layer).
// Feeding the summed matrix UNROUNDED into the GEMM equals the reference's
// per-relation tf32 GEMMs up to fp32 accumulation order.
__global__ void compute_eff(const float* __restrict__ Wr, const float* __restrict__ bl,
                            float* __restrict__ WrEff, float* __restrict__ bEff) {
    int t = blockIdx.x, l = blockIdx.y;
    int cnt = c_relcnt[t];
    for (int idx = threadIdx.x; idx < D * D; idx += blockDim.x) {
        float s = 0.f;
        for (int j = 0; j < cnt; j++)
            s += tf32r(Wr[(size_t)(l * NRELS + c_rels[t][j]) * D * D + idx]);
        WrEff[(size_t)(l * NTYPES + t) * D * D + idx] = s;
    }
    for (int idx = threadIdx.x; idx < D; idx += blockDim.x) {
        float s = 0.f;
        for (int j = 0; j < cnt; j++)
            s += bl[(size_t)(l * NRELS + c_rels[t][j]) * D + idx];
        bEff[(size_t)(l * NTYPES + t) * D + idx] = s;
    }
}

// ---------------- SGEMM: C[M,128] (+)= op(A[M,128]) @ op(B[128,128]) (+bias) ----
// op(A): optional per-row division by max(deg,1) (fp32 IEEE div, matching
// msg/deg[:,None]), then optional tf32 rounding. op(B): optional tf32 rounding.
// Accumulation in exact fp32. 64x128 tile, 256 threads, 8x4 per thread.
__global__ __launch_bounds__(256) void sgemm_k128(
    const float* __restrict__ A, const float* __restrict__ B,
    const float* __restrict__ bias, const float* __restrict__ deg,
    float* __restrict__ C, int M, int accum, int roundA, int roundB)
{
    __shared__ float As[16][64];
    __shared__ float Bs[16][128];
    const int tid = threadIdx.x;
    const int m0  = blockIdx.x * 64;
    const int cg  = tid & 31;
    const int rg  = tid >> 5;
    const int lr  = tid >> 2;
    const int lk  = (tid & 3) << 2;
    const int grow = m0 + lr;

    float dmax = 1.0f;
    if (deg != nullptr && grow < M) dmax = fmaxf(deg[grow], 1.0f);
    const bool arow = (grow < M);
    const float* Arow = A + (size_t)grow * D;

    float acc[8][4];
#pragma unroll
    for (int i = 0; i < 8; i++)
#pragma unroll
        for (int j = 0; j < 4; j++) acc[i][j] = 0.f;

    for (int k0 = 0; k0 < D; k0 += 16) {
        float4 av = make_float4(0.f, 0.f, 0.f, 0.f);
        if (arow) av = *(const float4*)(Arow + k0 + lk);
        if (deg != nullptr) { av.x /= dmax; av.y /= dmax; av.z /= dmax; av.w /= dmax; }
        if (roundA) { av.x = tf32r(av.x); av.y = tf32r(av.y); av.z = tf32r(av.z); av.w = tf32r(av.w); }
        As[lk + 0][lr] = av.x;
        As[lk + 1][lr] = av.y;
        As[lk + 2][lr] = av.z;
        As[lk + 3][lr] = av.w;
#pragma unroll
        for (int t = 0; t < 2; t++) {
            int idx = tid + t * 256;
            int bk = idx >> 5;
            int bn = (idx & 31) << 2;
            float4 bv = *(const float4*)&B[(size_t)(k0 + bk) * D + bn];
            if (roundB) { bv.x = tf32r(bv.x); bv.y = tf32r(bv.y); bv.z = tf32r(bv.z); bv.w = tf32r(bv.w); }
            *(float4*)&Bs[bk][bn] = bv;
        }
        __syncthreads();
#pragma unroll
        for (int k = 0; k < 16; k++) {
            float4 b  = *(float4*)&Bs[k][cg << 2];
            float4 a0 = *(float4*)&As[k][rg << 3];
            float4 a1 = *(float4*)&As[k][(rg << 3) + 4];
            float a[8] = {a0.x, a0.y, a0.z, a0.w, a1.x, a1.y, a1.z, a1.w};
#pragma unroll
            for (int i = 0; i < 8; i++) {
                acc[i][0] += a[i] * b.x;
                acc[i][1] += a[i] * b.y;
                acc[i][2] += a[i] * b.z;
                acc[i][3] += a[i] * b.w;
            }
        }
        __syncthreads();
    }
    const int n0 = cg << 2;
    float4 bi = make_float4(0.f, 0.f, 0.f, 0.f);
    if (bias != nullptr) bi = *(const float4*)&bias[n0];
#pragma unroll
    for (int i = 0; i < 8; i++) {
        int row = m0 + (rg << 3) + i;
        if (row < M) {
            float* cp = &C[(size_t)row * D + n0];
            float4 c = accum ? *(float4*)cp : make_float4(0.f, 0.f, 0.f, 0.f);
            c.x += acc[i][0] + bi.x;
            c.y += acc[i][1] + bi.y;
            c.z += acc[i][2] + bi.z;
            c.w += acc[i][3] + bi.w;
            *(float4*)cp = c;
        }
    }
}

// ---------------- scatter: one warp per edge, exact fp32 atomics ----------------
__global__ void scatter_agg(const float* __restrict__ xsrc, const int* __restrict__ ei, int E,
                            float* __restrict__ agg, float* __restrict__ deg)
{
    int w = (blockIdx.x * blockDim.x + threadIdx.x) >> 5;
    if (w >= E) return;
    int lane = threadIdx.x & 31;
    int r = ei[w];
    int c = ei[E + w];
    float4 v = *(const float4*)&xsrc[(size_t)r * D + (lane << 2)];
    float* d = &agg[(size_t)c * D + (lane << 2)];
    atomicAdd(d + 0, v.x);
    atomicAdd(d + 1, v.y);
    atomicAdd(d + 2, v.z);
    atomicAdd(d + 3, v.w);
    if (lane == 0) atomicAdd(&deg[c], 1.0f);
}

// ---------------- classifier ----------------
__global__ __launch_bounds__(256) void classifier_kernel(
    const float* __restrict__ xv, const float* __restrict__ xd,
    const int* __restrict__ eli,
    const float* __restrict__ W1, const float* __restrict__ b1,
    const float* __restrict__ w2, const float* __restrict__ b2,
    float* __restrict__ pred, int M)
{
    __shared__ float As[16][64];
    __shared__ float Bs[16][128];
    __shared__ int vidx[64];
    __shared__ int didx[64];
    const int tid = threadIdx.x;
    const int m0  = blockIdx.x * 64;
    if (tid < 64) {
        int r = m0 + tid;
        vidx[tid] = (r < M) ? eli[r] : 0;
    } else if (tid < 128) {
        int t = tid - 64, r = m0 + t;
        didx[t] = (r < M) ? eli[M + r] : 0;
    }
    __syncthreads();

    const int cg = tid & 31, rg = tid >> 5;
    const int lr = tid >> 2, lk = (tid & 3) << 2;
    const float* rowv = xv + (size_t)vidx[lr] * D;
    const float* rowd = xd + (size_t)didx[lr] * D;

    float acc[8][4];
#pragma unroll
    for (int i = 0; i < 8; i++)
#pragma unroll
        for (int j = 0; j < 4; j++) acc[i][j] = 0.f;

    for (int k0 = 0; k0 < 2 * D; k0 += 16) {
        float4 av;
        if (k0 < D) av = *(const float4*)(rowv + k0 + lk);
        else        av = *(const float4*)(rowd + (k0 - D) + lk);
        As[lk + 0][lr] = tf32r(av.x);
        As[lk + 1][lr] = tf32r(av.y);
        As[lk + 2][lr] = tf32r(av.z);
        As[lk + 3][lr] = tf32r(av.w);
#pragma unroll
        for (int t = 0; t < 2; t++) {
            int idx = tid + t * 256;
            int bk = idx >> 5;
            int bn = (idx & 31) << 2;
            float4 bv = *(const float4*)&W1[(size_t)(k0 + bk) * D + bn];
            bv.x = tf32r(bv.x); bv.y = tf32r(bv.y); bv.z = tf32r(bv.z); bv.w = tf32r(bv.w);
            *(float4*)&Bs[bk][bn] = bv;
        }
        __syncthreads();
#pragma unroll
        for (int k = 0; k < 16; k++) {
            float4 b  = *(float4*)&Bs[k][cg << 2];
            float4 a0 = *(float4*)&As[k][rg << 3];
            float4 a1 = *(float4*)&As[k][(rg << 3) + 4];
            float a[8] = {a0.x, a0.y, a0.z, a0.w, a1.x, a1.y, a1.z, a1.w};
#pragma unroll
            for (int i = 0; i < 8; i++) {
                acc[i][0] += a[i] * b.x;
                acc[i][1] += a[i] * b.y;
                acc[i][2] += a[i] * b.z;
                acc[i][3] += a[i] * b.w;
            }
        }
        __syncthreads();
    }
    const int n0 = cg << 2;
    float4 bi = *(const float4*)&b1[n0];
    float4 w  = *(const float4*)&w2[n0];   // h @ cls_w2 kept exact fp32 (gemv path)
    float b2v = b2[0];
#pragma unroll
    for (int i = 0; i < 8; i++) {
        float h0 = fmaxf(acc[i][0] + bi.x, 0.f);
        float h1 = fmaxf(acc[i][1] + bi.y, 0.f);
        float h2 = fmaxf(acc[i][2] + bi.z, 0.f);
        float h3 = fmaxf(acc[i][3] + bi.w, 0.f);
        float p = h0 * w.x + h1 * w.y + h2 * w.z + h3 * w.w;
#pragma unroll
        for (int off = 16; off; off >>= 1) p += __shfl_down_sync(0xffffffffu, p, off);
        if (cg == 0) {
            int row = m0 + (rg << 3) + i;
            if (row < M) pred[row] = p + b2v;
        }
    }
}

// ---------------- loss ----------------
__global__ void loss_partial(const float* __restrict__ pred, const float* __restrict__ label,
                             float* __restrict__ part, int M)
{
    __shared__ float sh[256];
    float s = 0.f;
    for (int i = blockIdx.x * blockDim.x + threadIdx.x; i < M; i += gridDim.x * blockDim.x) {
        float z = pred[i];
        float sp = fmaxf(z, 0.f) + log1pf(expf(-fabsf(z)));
        s += sp - z * label[i];
    }
    sh[threadIdx.x] = s;
    __syncthreads();
    for (int o = 128; o; o >>= 1) {
        if (threadIdx.x < o) sh[threadIdx.x] += sh[threadIdx.x + o];
        __syncthreads();
    }
    if (threadIdx.x == 0) part[blockIdx.x] = sh[0];
}

__global__ void loss_final(const float* __restrict__ part, float* __restrict__ out)
{
    __shared__ float sh[256];
    sh[threadIdx.x] = part[threadIdx.x];
    __syncthreads();
    for (int o = 128; o; o >>= 1) {
        if (threadIdx.x < o) sh[threadIdx.x] += sh[threadIdx.x + o];
        __syncthreads();
    }
    if (threadIdx.x == 0) out[0] = sh[0] * (1.0f / (float)E_LABEL);
}

// ---------------- launcher ----------------
extern "C" void kernel_launch(void* const* d_in, const int* in_sizes, int n_in,
                              void* d_out, int out_size)
{
    (void)n_in; (void)out_size;
    // Input-layout dispatch: signature order (node_ids 0-5, embs 6-11) has
    // in_sizes[1] == N[visit] == 100000; interleaved dict order has
    // in_sizes[1] == 20000*128 == 2560000 (emb_patient). All other indices
    // (ei, weights, labels) are identical across both layouts.
    const bool interleaved = (in_sizes[1] != 100000);
    const float* emb[NTYPES];
    for (int t = 0; t < NTYPES; t++)
        emb[t] = (const float*)d_in[interleaved ? (2 * t + 1) : (6 + t)];
    const int* ei[NRELS];
    for (int r = 0; r < NRELS; r++) ei[r] = (const int*)d_in[12 + r];
    const float* Wl  = (const float*)d_in[22];
    const float* bl  = (const float*)d_in[23];
    const float* Wr  = (const float*)d_in[24];
    const float* w1  = (const float*)d_in[25];
    const float* b1  = (const float*)d_in[26];
    const float* w2  = (const float*)d_in[27];
    const float* b2  = (const float*)d_in[28];
    const int*   eli  = (const int*)d_in[29];
    const float* elab = (const float*)d_in[30];

    float *x0, *x1, *agg, *deg, *wre, *bef, *part;
    cudaGetSymbolAddress((void**)&x0,  g_x0);
    cudaGetSymbolAddress((void**)&x1,  g_x1);
    cudaGetSymbolAddress((void**)&agg, g_agg);
    cudaGetSymbolAddress((void**)&deg, g_deg);
    cudaGetSymbolAddress((void**)&wre, g_wre);
    cudaGetSymbolAddress((void**)&bef, g_bef);
    cudaGetSymbolAddress((void**)&part, g_part);

    // x0 = embeddings (node_id_* are arange -> gather is identity)
    for (int t = 0; t < NTYPES; t++)
        cudaMemcpyAsync(x0 + (size_t)kOFF[t] * D, emb[t],
                        (size_t)kN[t] * D * sizeof(float),
                        cudaMemcpyDeviceToDevice, 0);

    compute_eff<<<dim3(NTYPES, NLAYERS), 256>>>(Wr, bl, wre, bef);

    float* xb[2] = {x0, x1};
    for (int l = 0; l < NLAYERS; l++) {
        const float* xin = xb[l & 1];
        float* xout = xb[(l & 1) ^ 1];

        // out[t] = tf32(x[t]) @ (sum_r tf32(W_r)) + sum_r b_l   (roundA only)
        for (int t = 0; t < NTYPES; t++)
            sgemm_k128<<<(kN[t] + 63) / 64, 256>>>(
                xin + (size_t)kOFF[t] * D,
                wre + (size_t)(l * NTYPES + t) * D * D,
                bef + (size_t)(l * NTYPES + t) * D,
                nullptr, xout + (size_t)kOFF[t] * D, kN[t],
                /*accum=*/0, /*roundA=*/1, /*roundB=*/0);

        // Every relation aggregate-first: exact fp32 mean, then tf32 GEMM.
        for (int r = 0; r < NRELS; r++) {
            int dt = kRD[r], st = kRS[r], E = kRE[r];
            size_t nagg = (size_t)kN[dt] * D;
            int zb = (int)((nagg + 255) / 256);
            if (zb > 8192) zb = 8192;
            kzero<<<zb, 256>>>(agg, nagg);
            kzero<<<(kN[dt] + 255) / 256, 256>>>(deg, (size_t)kN[dt]);
            scatter_agg<<<(E * 32 + 255) / 256, 256>>>(
                xin + (size_t)kOFF[st] * D, ei[r], E, agg, deg);
            sgemm_k128<<<(kN[dt] + 63) / 64, 256>>>(
                agg, Wl + (size_t)(l * NRELS + r) * D * D,
                nullptr, deg, xout + (size_t)kOFF[dt] * D, kN[dt],
                /*accum=*/1, /*roundA=*/1, /*roundB=*/1);
        }

        if (l < NLAYERS - 1)
            krelu<<<4096, 256>>>(xout, (size_t)NTOT * D);
    }

    float* outp = (float*)d_out;
    float* pred = outp + 1;
    classifier_kernel<<<(E_LABEL + 63) / 64, 256>>>(
        xb[0] + (size_t)kOFF[1] * D, xb[0] + (size_t)kOFF[5] * D,
        eli, w1, b1, w2, b2, pred, E_LABEL);
    loss_partial<<<256, 256>>>(pred, elab, part, E_LABEL);
    loss_final<<<1, 256>>>(part, outp);
}